// round 4
// baseline (speedup 1.0000x reference)
#include <cuda_runtime.h>

#define FULLMASK 0xffffffffu

__device__ __forceinline__ float2 cmul(float2 a, float2 b){
    return make_float2(a.x*b.x - a.y*b.y, a.x*b.y + a.y*b.x);
}
__device__ __forceinline__ float2 cadd(float2 a, float2 b){
    return make_float2(a.x + b.x, a.y + b.y);
}
__device__ __forceinline__ float2 cmadd(float2 acc, float2 a, float2 b){
    acc.x = fmaf(a.x, b.x, fmaf(-a.y, b.y, acc.x));
    acc.y = fmaf(a.x, b.y, fmaf( a.y, b.x, acc.y));
    return acc;
}
__device__ __forceinline__ float2 shflx(float2 v, int m){
    float2 r;
    r.x = __shfl_xor_sync(FULLMASK, v.x, m);
    r.y = __shfl_xor_sync(FULLMASK, v.y, m);
    return r;
}
__device__ __forceinline__ void gapply(float2 &a0, float2 &a1,
                                       float2 g00, float2 g01, float2 g10, float2 g11){
    float2 n0 = cadd(cmul(g00, a0), cmul(g01, a1));
    float2 n1 = cadd(cmul(g10, a0), cmul(g11, a1));
    a0 = n0; a1 = n1;
}

// One CTA per sample. 4096 amplitudes = 256 threads x 16 register-resident complex.
// Index bit layout of amplitude k = tid*16 + m:
//   bits 0..3  = m      (wires 11..8)
//   bits 4..8  = lane   (wires 7..3)
//   bits 9..11 = warp   (wires 2..0)
__global__ void __launch_bounds__(256) qsim_kernel(
    const float* __restrict__ x,        // [B,12]
    const float* __restrict__ params,   // [3,12,3]
    const float* __restrict__ hw,       // [12]
    const float* __restrict__ hb,       // [1]
    float* __restrict__ out)            // [B]
{
    __shared__ float2 ex[4096];         // 32KB exchange buffer (warp-dim transform)
    __shared__ float2 sW[3][8][8];      // per-layer 8x8 warp transform (wires 0-2 + C(0,1)+C(1,2))
    __shared__ float2 sG[3][12][4];     // fused RY*RZ*RY 2x2 gates
    __shared__ float  sC[12], sS[12], sHw[12];
    __shared__ float  sRed[8];

    const int tid  = threadIdx.x;
    const int lane = tid & 31;
    const int warp = tid >> 5;
    const int b    = blockIdx.x;

    // ---- Stage 0: gate precompute (sample-independent fused gates + per-sample RX angles)
    if (tid < 36){
        int l = tid / 12, i = tid % 12;
        float pa = params[(l*12 + i)*3 + 0];
        float pb = params[(l*12 + i)*3 + 1];
        float pc = params[(l*12 + i)*3 + 2];
        float ca, sa, cb, sb, cc, sc;
        sincosf(0.5f*pa, &sa, &ca);
        sincosf(0.5f*pb, &sb, &cb);
        sincosf(0.5f*pc, &sc, &cc);
        // g = RY(pc) * RZ(pb) * RY(pa);  em=e^{-i pb/2}, ep=conj(em)
        float2 em = make_float2(cb, -sb);
        float2 ep = make_float2(cb,  sb);
        float ccca = cc*ca, scsa = sc*sa, ccsa = cc*sa, scca = sc*ca;
        sG[l][i][0] = make_float2( ccca*em.x - scsa*ep.x,  ccca*em.y - scsa*ep.y);
        sG[l][i][1] = make_float2(-ccsa*em.x - scca*ep.x, -ccsa*em.y - scca*ep.y);
        sG[l][i][2] = make_float2( scca*em.x + ccsa*ep.x,  scca*em.y + ccsa*ep.y);
        sG[l][i][3] = make_float2(-scsa*em.x + ccca*ep.x, -scsa*em.y + ccca*ep.y);
    } else if (tid >= 64 && tid < 76){
        int i = tid - 64;
        float s, c;
        sincosf(0.5f * x[b*12 + i], &s, &c);
        sC[i] = c; sS[i] = s;
        sHw[i] = hw[i];
    }
    __syncthreads();

    // Build W_l[v][w'] = (G0 (x) G1 (x) G2)[sigma^-1(v)][w'] with the CNOT(0,1),CNOT(1,2)
    // permutations folded in.  Warp-index bits: bit2=wire0, bit1=wire1, bit0=wire2.
    if (tid < 192){
        int l = tid >> 6, r = tid & 63, v = r >> 3, wp = r & 7;
        int u = v ^ ((v >> 1) & 1);        // inverse of CNOT(1,2): ctrl bit1 -> tgt bit0
        u ^= ((u >> 2) & 1) << 1;          // inverse of CNOT(0,1): ctrl bit2 -> tgt bit1
        float2 t = cmul(sG[l][0][((u>>2)&1)*2 + ((wp>>2)&1)],
                        sG[l][1][((u>>1)&1)*2 + ((wp>>1)&1)]);
        t = cmul(t, sG[l][2][(u&1)*2 + (wp&1)]);
        sW[l][v][wp] = t;
    }
    __syncthreads();

    // ---- Init: product state after RX encoding layer (RX column 0 = [cos, -i sin])
    float2 a[16];
    {
        float2 base = make_float2(1.f, 0.f);
        #pragma unroll
        for (int i = 0; i < 8; i++){
            int v = (tid >> (7 - i)) & 1;   // wire i (0..7) lives at index bit 11-i = tid bit 7-i
            float2 f = v ? make_float2(0.f, -sS[i]) : make_float2(sC[i], 0.f);
            base = cmul(base, f);
        }
        float2 t8[2], t9[4], t10[8];
        t8[0] = make_float2(base.x*sC[8], base.y*sC[8]);
        t8[1] = cmul(base, make_float2(0.f, -sS[8]));
        #pragma unroll
        for (int u = 0; u < 2; u++){
            t9[2*u]   = make_float2(t8[u].x*sC[9], t8[u].y*sC[9]);
            t9[2*u+1] = cmul(t8[u], make_float2(0.f, -sS[9]));
        }
        #pragma unroll
        for (int u = 0; u < 4; u++){
            t10[2*u]   = make_float2(t9[u].x*sC[10], t9[u].y*sC[10]);
            t10[2*u+1] = cmul(t9[u], make_float2(0.f, -sS[10]));
        }
        #pragma unroll
        for (int u = 0; u < 8; u++){
            a[2*u]   = make_float2(t10[u].x*sC[11], t10[u].y*sC[11]);
            a[2*u+1] = cmul(t10[u], make_float2(0.f, -sS[11]));
        }
    }

    // ---- 3 layers
    for (int l = 0; l < 3; l++){
        // Local gates: wires 8..11 <-> m bits 3..0 (register only)
        {
            float2 g00=sG[l][8][0], g01=sG[l][8][1], g10=sG[l][8][2], g11=sG[l][8][3];
            #pragma unroll
            for (int m = 0; m < 8; m++) gapply(a[m], a[m+8], g00, g01, g10, g11);
        }
        {
            float2 g00=sG[l][9][0], g01=sG[l][9][1], g10=sG[l][9][2], g11=sG[l][9][3];
            #pragma unroll
            for (int m = 0; m < 16; m++) if (!(m & 4)) gapply(a[m], a[m+4], g00, g01, g10, g11);
        }
        {
            float2 g00=sG[l][10][0], g01=sG[l][10][1], g10=sG[l][10][2], g11=sG[l][10][3];
            #pragma unroll
            for (int m = 0; m < 16; m++) if (!(m & 2)) gapply(a[m], a[m+2], g00, g01, g10, g11);
        }
        {
            float2 g00=sG[l][11][0], g01=sG[l][11][1], g10=sG[l][11][2], g11=sG[l][11][3];
            #pragma unroll
            for (int m = 0; m < 16; m++) if (!(m & 1)) gapply(a[m], a[m+1], g00, g01, g10, g11);
        }

        // Lane gates: wires 3..7 <-> lane masks 16,8,4,2,1 (shuffle butterflies)
        #pragma unroll
        for (int w = 3; w < 8; w++){
            const int mask = 1 << (7 - w);
            float2 g00=sG[l][w][0], g01=sG[l][w][1], g10=sG[l][w][2], g11=sG[l][w][3];
            const bool hi = (lane & mask) != 0;
            #pragma unroll
            for (int m = 0; m < 16; m++){
                float2 o = shflx(a[m], mask);
                a[m] = hi ? cadd(cmul(g10, o), cmul(g11, a[m]))
                          : cadd(cmul(g00, a[m]), cmul(g01, o));
            }
        }

        // Warp-dim 8x8 transform: wires 0..2 gates + CNOT(0,1) + CNOT(1,2), one smem round-trip.
        __syncthreads();   // buffer free (prev layer's reads done / first use)
        #pragma unroll
        for (int m = 0; m < 16; m++) ex[(warp*16 + m)*32 + lane] = a[m];
        __syncthreads();
        {
            float2 Wr[8];
            #pragma unroll
            for (int wp = 0; wp < 8; wp++) Wr[wp] = sW[l][warp][wp];
            #pragma unroll
            for (int m = 0; m < 16; m++){
                float2 acc = make_float2(0.f, 0.f);
                #pragma unroll
                for (int wp = 0; wp < 8; wp++)
                    acc = cmadd(acc, Wr[wp], ex[(wp*16 + m)*32 + lane]);
                a[m] = acc;
            }
        }

        // CNOT chain tail (after C(0,1), C(1,2) already folded into W)
        // C(2,3): ctrl = warp bit0, tgt = lane bit4
        {
            const bool c = (warp & 1) != 0;
            #pragma unroll
            for (int m = 0; m < 16; m++){
                float2 o = shflx(a[m], 16);
                if (c) a[m] = o;
            }
        }
        // C(3,4)..C(6,7): (ctrl mask, tgt mask) = (16,8),(8,4),(4,2),(2,1) within lane bits
        #pragma unroll
        for (int j = 0; j < 4; j++){
            const int cm = 16 >> j, tm = 8 >> j;
            const bool c = (lane & cm) != 0;
            #pragma unroll
            for (int m = 0; m < 16; m++){
                float2 o = shflx(a[m], tm);
                if (c) a[m] = o;
            }
        }
        // C(7,8): ctrl = lane bit0, tgt = m bit3
        {
            const bool c = (lane & 1) != 0;
            #pragma unroll
            for (int m = 0; m < 8; m++){
                float2 t0 = a[m], t1 = a[m+8];
                a[m]   = c ? t1 : t0;
                a[m+8] = c ? t0 : t1;
            }
        }
        // C(8,9): ctrl m bit3, tgt m bit2
        #pragma unroll
        for (int m = 8; m < 12; m++){ float2 t = a[m]; a[m] = a[m+4]; a[m+4] = t; }
        // C(9,10): ctrl m bit2, tgt m bit1
        { float2 t;
          t=a[4];  a[4]=a[6];   a[6]=t;
          t=a[5];  a[5]=a[7];   a[7]=t;
          t=a[12]; a[12]=a[14]; a[14]=t;
          t=a[13]; a[13]=a[15]; a[15]=t; }
        // C(10,11): ctrl m bit1, tgt m bit0
        { float2 t;
          t=a[2];  a[2]=a[3];   a[3]=t;
          t=a[6];  a[6]=a[7];   a[7]=t;
          t=a[10]; a[10]=a[11]; a[11]=t;
          t=a[14]; a[14]=a[15]; a[15]=t; }
    }

    // ---- Readout: out[b] = sum_k |a_k|^2 * (sum_i w_i * (+1/-1 per bit)) + head_b
    float basec = 0.f;
    #pragma unroll
    for (int i = 0; i < 8; i++){
        float w = sHw[i];
        basec += ((tid >> (7 - i)) & 1) ? -w : w;
    }
    float partial = 0.f;
    #pragma unroll
    for (int m = 0; m < 16; m++){
        float c = basec;
        c += (m & 8) ? -sHw[8]  : sHw[8];
        c += (m & 4) ? -sHw[9]  : sHw[9];
        c += (m & 2) ? -sHw[10] : sHw[10];
        c += (m & 1) ? -sHw[11] : sHw[11];
        partial = fmaf(fmaf(a[m].x, a[m].x, a[m].y*a[m].y), c, partial);
    }
    #pragma unroll
    for (int off = 16; off; off >>= 1)
        partial += __shfl_down_sync(FULLMASK, partial, off);
    if (lane == 0) sRed[warp] = partial;
    __syncthreads();
    if (tid == 0){
        float s = hb[0];
        #pragma unroll
        for (int w = 0; w < 8; w++) s += sRed[w];
        out[b] = s;
    }
}

extern "C" void kernel_launch(void* const* d_in, const int* in_sizes, int n_in,
                              void* d_out, int out_size)
{
    const float* x      = (const float*)d_in[0];
    const float* params = (const float*)d_in[1];
    const float* hw     = (const float*)d_in[2];
    const float* hb     = (const float*)d_in[3];
    float* out = (float*)d_out;
    (void)in_sizes; (void)n_in;
    qsim_kernel<<<out_size, 256>>>(x, params, hw, hb, out);
}